// round 10
// baseline (speedup 1.0000x reference)
#include <cuda_runtime.h>
#include <cuda_fp16.h>
#include <cstdint>
#include <math.h>

// Problem constants
// B=16, N=M=512, VS=2048, QS=1024, OS=2048, H=16, DH=128
#define ROWS      8192        // B * 512
#define TRANS_W   6144        // 3 * OS
#define OS_W      2048

// -------------------- scratch (device globals; no allocations allowed) -----
__device__ float g_vtrans[(size_t)ROWS * TRANS_W];
__device__ float g_qtrans[(size_t)ROWS * TRANS_W];
__device__ float g_vupd  [(size_t)ROWS * OS_W];
__device__ float g_qupd  [(size_t)ROWS * OS_W];

__device__ __forceinline__ unsigned pack_h2(float lo, float hi) {
    __half2 h = __floats2half2_rn(lo, hi);
    return *(unsigned*)&h;
}

// fp16 MMA, fp32 accumulate: D[16x8] += A[16x16] * B[16x8]
__device__ __forceinline__ void mma_f16(float c[4], const unsigned a[4], const unsigned b[2]) {
    asm volatile(
        "mma.sync.aligned.m16n8k16.row.col.f32.f16.f16.f32 "
        "{%0,%1,%2,%3}, {%4,%5,%6,%7}, {%8,%9}, {%0,%1,%2,%3};\n"
        : "+f"(c[0]), "+f"(c[1]), "+f"(c[2]), "+f"(c[3])
        : "r"(a[0]), "r"(a[1]), "r"(a[2]), "r"(a[3]),
          "r"(b[0]), "r"(b[1]));
}

__device__ __forceinline__ void ldsm_x4(unsigned r[4], unsigned saddr) {
    asm volatile(
        "ldmatrix.sync.aligned.m8n8.x4.shared.b16 {%0,%1,%2,%3}, [%4];\n"
        : "=r"(r[0]), "=r"(r[1]), "=r"(r[2]), "=r"(r[3])
        : "r"(saddr));
}

// ============================================================================
// FP16 tensor-core GEMM (fp32 accum), CTA 128x128, warp 64x32, BK=16,
// double-buffered, dual-A concat. A-fragments via ldmatrix.x4 (4 LDSM
// replace 16 scalar LDS per chunk per warp).
// ============================================================================
#define BM 128
#define BN 128
#define BK 16
#define ASTRIDE 12
#define BSTRIDE 136

__global__ void __launch_bounds__(256, 2)
hgemm_kernel(const float* __restrict__ A1, int K1,
             const float* __restrict__ A2, int K2,
             const float* __restrict__ Bm,
             float* __restrict__ C,
             const float* __restrict__ bias, const float* __restrict__ mask,
             int N)
{
    __shared__ unsigned As[2][BM][ASTRIDE];
    __shared__ unsigned Bs[2][8][BSTRIDE];

    const int tid  = threadIdx.x;
    const int lane = tid & 31;
    const int warp = tid >> 5;
    const int gid  = lane >> 2;
    const int tig  = lane & 3;
    const int wm = (warp >> 2) * 64;
    const int wn = (warp & 3) * 32;

    const int rowBase = blockIdx.y * BM;
    const int colBase = blockIdx.x * BN;

    const int aR0 = tid >> 2;
    const int aK0 = (tid & 3) << 2;
    const int aR1 = aR0 + 64;
    const int pr  = tid >> 5;
    const int c0  = (tid & 31) << 2;

    const int K = K1 + K2;
    const int kChunks = K / BK;

    const float* P1r0 = (K1 > 0) ? A1 + (size_t)(rowBase + aR0) * K1 : nullptr;
    const float* P1r1 = (K1 > 0) ? A1 + (size_t)(rowBase + aR1) * K1 : nullptr;
    const float* P2r0 = (K2 > 0) ? A2 + (size_t)(rowBase + aR0) * K2 - K1 : nullptr;
    const float* P2r1 = (K2 > 0) ? A2 + (size_t)(rowBase + aR1) * K2 - K1 : nullptr;

    const float* Blo = Bm + (size_t)(2 * pr)     * N + colBase + c0;
    const float* Bhi = Bm + (size_t)(2 * pr + 1) * N + colBase + c0;

    // ldmatrix source addresses (per mt, per stage; lane-dependent)
    // lanes 0-15: rows wm+mt*16+(lane&15), pair-offset 0; lanes 16-31: same rows, +16B
    const unsigned asBase = (unsigned)__cvta_generic_to_shared(&As[0][0][0]);
    const unsigned aStageBytes = BM * ASTRIDE * 4;
    const unsigned aLaneOff =
        (unsigned)((wm + (lane & 15)) * ASTRIDE * 4 + (lane >> 4) * 16);

    float acc[4][4][4];
#pragma unroll
    for (int i = 0; i < 4; i++)
#pragma unroll
        for (int j = 0; j < 4; j++)
#pragma unroll
            for (int r = 0; r < 4; r++) acc[i][j][r] = 0.0f;

    float4 ra0, ra1, rblo, rbhi;
    {
        const float* s0 = (0 < K1) ? P1r0 : P2r0;
        const float* s1 = (0 < K1) ? P1r1 : P2r1;
        ra0 = *(const float4*)(s0 + aK0);
        ra1 = *(const float4*)(s1 + aK0);
        rblo = *(const float4*)Blo;
        rbhi = *(const float4*)Bhi;
    }

    for (int ck = 0; ck < kChunks; ck++) {
        const int cur = ck & 1;

        {
            uint2 u0 = { pack_h2(ra0.x, ra0.y), pack_h2(ra0.z, ra0.w) };
            uint2 u1 = { pack_h2(ra1.x, ra1.y), pack_h2(ra1.z, ra1.w) };
            *(uint2*)&As[cur][aR0][aK0 >> 1] = u0;
            *(uint2*)&As[cur][aR1][aK0 >> 1] = u1;
        }
        {
            uint4 u;
            u.x = pack_h2(rblo.x, rbhi.x);
            u.y = pack_h2(rblo.y, rbhi.y);
            u.z = pack_h2(rblo.z, rbhi.z);
            u.w = pack_h2(rblo.w, rbhi.w);
            *(uint4*)&Bs[cur][pr][c0] = u;
        }
        __syncthreads();

        if (ck + 1 < kChunks) {
            const int k0n = (ck + 1) * BK;
            const float* s0 = (k0n < K1) ? P1r0 : P2r0;
            const float* s1 = (k0n < K1) ? P1r1 : P2r1;
            ra0 = *(const float4*)(s0 + k0n + aK0);
            ra1 = *(const float4*)(s1 + k0n + aK0);
            rblo = *(const float4*)(Blo + (size_t)k0n * N);
            rbhi = *(const float4*)(Bhi + (size_t)k0n * N);
        }

        // A-fragments: 4x ldmatrix.x4
        unsigned afr[4][4];
        {
            const unsigned stageAddr = asBase + (unsigned)cur * aStageBytes + aLaneOff;
#pragma unroll
            for (int mt = 0; mt < 4; mt++)
                ldsm_x4(afr[mt], stageAddr + (unsigned)(mt * 16 * ASTRIDE * 4));
        }
        // B-fragments: scalar LDS (layout conflict-free)
        unsigned bfr[4][2];
#pragma unroll
        for (int nt = 0; nt < 4; nt++) {
            const int c = wn + nt * 8 + gid;
            bfr[nt][0] = Bs[cur][tig][c];
            bfr[nt][1] = Bs[cur][tig + 4][c];
        }
#pragma unroll
        for (int mt = 0; mt < 4; mt++)
#pragma unroll
            for (int nt = 0; nt < 4; nt++)
                mma_f16(acc[mt][nt], afr[mt], bfr[nt]);
    }

#pragma unroll
    for (int mt = 0; mt < 4; mt++) {
        const int r0 = rowBase + wm + mt * 16 + gid;
        const int r1 = r0 + 8;
        const float m0 = mask ? mask[r0] : 1.0f;
        const float m1 = mask ? mask[r1] : 1.0f;
#pragma unroll
        for (int nt = 0; nt < 4; nt++) {
            const int c = colBase + wn + nt * 8 + (tig << 1);
            const float b0 = bias[c], b1 = bias[c + 1];
            float2 v0, v1;
            v0.x = fmaxf(acc[mt][nt][0] + b0, 0.0f) * m0;
            v0.y = fmaxf(acc[mt][nt][1] + b1, 0.0f) * m0;
            v1.x = fmaxf(acc[mt][nt][2] + b0, 0.0f) * m1;
            v1.y = fmaxf(acc[mt][nt][3] + b1, 0.0f) * m1;
            *(float2*)(C + (size_t)r0 * N + c) = v0;
            *(float2*)(C + (size_t)r1 * N + c) = v1;
        }
    }
}

// ============================================================================
// FP16 tensor-core flash attention (unchanged from R8, passing).
// ============================================================================
struct AttnSmem3 {
    unsigned Qh[128][68];
    unsigned Kh[64][68];
    unsigned Vh[32][136];
    unsigned Ps[128][36];
    float    Mk[64];
};

__global__ void __launch_bounds__(256)
attn_mma_kernel(const float* __restrict__ Tq, const float* __restrict__ Tk,
                const float* __restrict__ maskK, float* __restrict__ out)
{
    extern __shared__ char smem_raw[];
    AttnSmem3& sm = *reinterpret_cast<AttnSmem3*>(smem_raw);

    const int b  = blockIdx.z;
    const int h  = blockIdx.y;
    const int qt = blockIdx.x;
    const int tid  = threadIdx.x;
    const int lane = tid & 31;
    const int warp = tid >> 5;
    const int r0   = warp * 16;
    const int gid  = lane >> 2;
    const int tig  = lane & 3;
    const float SCALE = 0.08838834764831845f;

    const float* qbase = Tq + (size_t)(b * 512 + qt * 128) * 6144 + 2048 + h * 128;
#pragma unroll
    for (int it = 0; it < 16; it++) {
        int lin = it * 256 + tid;
        int r = lin >> 5, c4 = (lin & 31) << 2;
        float4 v = *(const float4*)(qbase + (size_t)r * 6144 + c4);
        uint2 u = { pack_h2(v.x, v.y), pack_h2(v.z, v.w) };
        *(uint2*)&sm.Qh[r][c4 >> 1] = u;
    }

    float m_i[2] = { -INFINITY, -INFINITY };
    float l_i[2] = { 0.0f, 0.0f };
    float oacc[16][4];
#pragma unroll
    for (int nt = 0; nt < 16; nt++)
#pragma unroll
        for (int j = 0; j < 4; j++) oacc[nt][j] = 0.0f;

    const float* kbase = Tk + (size_t)b * 512 * 6144 + h * 128;
    const float* vbase = kbase + 4096;

    const int vpr = tid >> 5;
    const int vc0 = (tid & 31) << 2;

    for (int kt = 0; kt < 8; kt++) {
        __syncthreads();

#pragma unroll
        for (int it = 0; it < 8; it++) {
            int lin = it * 256 + tid;
            int r = lin >> 5, c4 = (lin & 31) << 2;
            float4 kv = *(const float4*)(kbase + (size_t)(kt * 64 + r) * 6144 + c4);
            uint2 u = { pack_h2(kv.x, kv.y), pack_h2(kv.z, kv.w) };
            *(uint2*)&sm.Kh[r][c4 >> 1] = u;
        }
#pragma unroll
        for (int it = 0; it < 4; it++) {
            int p = it * 8 + vpr;
            const float* vlo = vbase + (size_t)(kt * 64 + 2 * p)     * 6144 + vc0;
            const float* vhi = vbase + (size_t)(kt * 64 + 2 * p + 1) * 6144 + vc0;
            float4 lo = *(const float4*)vlo;
            float4 hi = *(const float4*)vhi;
            uint4 u;
            u.x = pack_h2(lo.x, hi.x);
            u.y = pack_h2(lo.y, hi.y);
            u.z = pack_h2(lo.z, hi.z);
            u.w = pack_h2(lo.w, hi.w);
            *(uint4*)&sm.Vh[p][vc0] = u;
        }
        if (tid < 64) sm.Mk[tid] = maskK[b * 512 + kt * 64 + tid];
        __syncthreads();

        float c[8][4];
#pragma unroll
        for (int nt = 0; nt < 8; nt++)
#pragma unroll
            for (int j = 0; j < 4; j++) c[nt][j] = 0.0f;

#pragma unroll
        for (int ks = 0; ks < 8; ks++) {
            const int pd = ks * 8 + tig;
            unsigned a[4];
            a[0] = sm.Qh[r0 + gid][pd];
            a[1] = sm.Qh[r0 + gid + 8][pd];
            a[2] = sm.Qh[r0 + gid][pd + 4];
            a[3] = sm.Qh[r0 + gid + 8][pd + 4];
#pragma unroll
            for (int nt = 0; nt < 8; nt++) {
                unsigned bf[2];
                bf[0] = sm.Kh[nt * 8 + gid][pd];
                bf[1] = sm.Kh[nt * 8 + gid][pd + 4];
                mma_f16(c[nt], a, bf);
            }
        }

#pragma unroll
        for (int nt = 0; nt < 8; nt++) {
            const int col = nt * 8 + tig * 2;
            const float k0m = sm.Mk[col];
            const float k1m = sm.Mk[col + 1];
            c[nt][0] = (k0m != 0.0f) ? c[nt][0] * SCALE : -INFINITY;
            c[nt][1] = (k1m != 0.0f) ? c[nt][1] * SCALE : -INFINITY;
            c[nt][2] = (k0m != 0.0f) ? c[nt][2] * SCALE : -INFINITY;
            c[nt][3] = (k1m != 0.0f) ? c[nt][3] * SCALE : -INFINITY;
        }

#pragma unroll
        for (int j = 0; j < 2; j++) {
            float tmax = -INFINITY;
#pragma unroll
            for (int nt = 0; nt < 8; nt++)
                tmax = fmaxf(tmax, fmaxf(c[nt][j * 2], c[nt][j * 2 + 1]));
            tmax = fmaxf(tmax, __shfl_xor_sync(0xffffffffu, tmax, 1));
            tmax = fmaxf(tmax, __shfl_xor_sync(0xffffffffu, tmax, 2));
            float mnew  = fmaxf(m_i[j], tmax);
            float msafe = (mnew == -INFINITY) ? 0.0f : mnew;
            float corr  = __expf(m_i[j] - msafe);
            float lsum = 0.0f;
            const int row = r0 + gid + j * 8;
#pragma unroll
            for (int nt = 0; nt < 8; nt++) {
                float p0 = __expf(c[nt][j * 2]     - msafe);
                float p1 = __expf(c[nt][j * 2 + 1] - msafe);
                lsum += p0 + p1;
                sm.Ps[row][nt * 4 + tig] = pack_h2(p0, p1);
            }
            lsum += __shfl_xor_sync(0xffffffffu, lsum, 1);
            lsum += __shfl_xor_sync(0xffffffffu, lsum, 2);
            l_i[j] = l_i[j] * corr + lsum;
            m_i[j] = mnew;
#pragma unroll
            for (int nt = 0; nt < 16; nt++) {
                oacc[nt][j * 2]     *= corr;
                oacc[nt][j * 2 + 1] *= corr;
            }
        }
        __syncwarp();

#pragma unroll
        for (int ks = 0; ks < 4; ks++) {
            const int pk = ks * 8 + tig;
            unsigned a[4];
            a[0] = sm.Ps[r0 + gid][pk];
            a[1] = sm.Ps[r0 + gid + 8][pk];
            a[2] = sm.Ps[r0 + gid][pk + 4];
            a[3] = sm.Ps[r0 + gid + 8][pk + 4];
#pragma unroll
            for (int nt = 0; nt < 16; nt++) {
                unsigned bf[2];
                bf[0] = sm.Vh[ks * 8 + tig][nt * 8 + gid];
                bf[1] = sm.Vh[ks * 8 + tig + 4][nt * 8 + gid];
                mma_f16(oacc[nt], a, bf);
            }
        }
    }

#pragma unroll
    for (int j = 0; j < 2; j++) {
        const float inv = (l_i[j] > 0.0f) ? (1.0f / l_i[j]) : 0.0f;
        const size_t orow = (size_t)(b * 512 + qt * 128 + r0 + gid + j * 8);
        float* op = out + orow * 2048 + h * 128 + tig * 2;
#pragma unroll
        for (int nt = 0; nt < 16; nt++) {
            float2 o;
            o.x = oacc[nt][j * 2]     * inv;
            o.y = oacc[nt][j * 2 + 1] * inv;
            *(float2*)(op + nt * 8) = o;
        }
    }
}

// ============================================================================
extern "C" void kernel_launch(void* const* d_in, const int* in_sizes, int n_in,
                              void* d_out, int out_size)
{
    (void)in_sizes; (void)n_in; (void)out_size;
    const float* v     = (const float*)d_in[0];
    const float* q     = (const float*)d_in[1];
    const float* vmask = (const float*)d_in[2];
    const float* qmask = (const float*)d_in[3];
    const float* Wv    = (const float*)d_in[4];
    const float* bv    = (const float*)d_in[5];
    const float* Wq    = (const float*)d_in[6];
    const float* bq    = (const float*)d_in[7];
    const float* Wvo   = (const float*)d_in[8];
    const float* bvo   = (const float*)d_in[9];
    const float* Wqo   = (const float*)d_in[10];
    const float* bqo   = (const float*)d_in[11];

    float* out_v = (float*)d_out;
    float* out_q = out_v + (size_t)ROWS * OS_W;

    float *vtrans, *qtrans, *vupd, *qupd;
    cudaGetSymbolAddress((void**)&vtrans, g_vtrans);
    cudaGetSymbolAddress((void**)&qtrans, g_qtrans);
    cudaGetSymbolAddress((void**)&vupd,   g_vupd);
    cudaGetSymbolAddress((void**)&qupd,   g_qupd);

    cudaFuncSetAttribute(attn_mma_kernel, cudaFuncAttributeMaxDynamicSharedMemorySize,
                         (int)sizeof(AttnSmem3));

    dim3 blk(256);

    // 1) v_trans = relu(v @ Wv + bv) * v_mask     [8192,6144] K=2048
    hgemm_kernel<<<dim3(TRANS_W / BN, ROWS / BM), blk>>>(
        v, 2048, nullptr, 0, Wv, vtrans, bv, vmask, TRANS_W);
    // 2) q_trans = relu(q @ Wq + bq) * q_mask     [8192,6144] K=1024
    hgemm_kernel<<<dim3(TRANS_W / BN, ROWS / BM), blk>>>(
        q, 1024, nullptr, 0, Wq, qtrans, bq, qmask, TRANS_W);

    // 3) q2v attention -> v_update
    attn_mma_kernel<<<dim3(4, 16, 16), blk, sizeof(AttnSmem3)>>>(vtrans, qtrans, qmask, vupd);
    // 4) v2q attention -> q_update
    attn_mma_kernel<<<dim3(4, 16, 16), blk, sizeof(AttnSmem3)>>>(qtrans, vtrans, vmask, qupd);

    // 5) updated_v = relu([v | v_update] @ Wvo + bvo)   (fused concat GEMM)
    hgemm_kernel<<<dim3(OS_W / BN, ROWS / BM), blk>>>(
        v, 2048, vupd, 2048, Wvo, out_v, bvo, nullptr, OS_W);
    // 6) updated_q = relu([q | q_update] @ Wqo + bqo)
    hgemm_kernel<<<dim3(OS_W / BN, ROWS / BM), blk>>>(
        q, 1024, qupd, 2048, Wqo, out_q, bqo, nullptr, OS_W);
}

// round 11
// speedup vs baseline: 1.1284x; 1.1284x over previous
#include <cuda_runtime.h>
#include <cuda_fp16.h>
#include <math.h>

// Problem constants
// B=16, N=M=512, VS=2048, QS=1024, OS=2048, H=16, DH=128
#define ROWS      8192        // B * 512
#define TRANS_W   6144        // 3 * OS
#define OS_W      2048

// -------------------- fp16 scratch (device globals; no allocations) --------
__device__ __half gh_v     [(size_t)ROWS * 2048];
__device__ __half gh_q     [(size_t)ROWS * 1024];
__device__ __half gh_Wv    [(size_t)2048 * TRANS_W];
__device__ __half gh_Wq    [(size_t)1024 * TRANS_W];
__device__ __half gh_Wvo   [(size_t)4096 * OS_W];
__device__ __half gh_Wqo   [(size_t)3072 * OS_W];
__device__ __half gh_vtrans[(size_t)ROWS * TRANS_W];
__device__ __half gh_qtrans[(size_t)ROWS * TRANS_W];
__device__ __half gh_vupd  [(size_t)ROWS * OS_W];
__device__ __half gh_qupd  [(size_t)ROWS * OS_W];

// fp16 MMA, fp32 accumulate: D[16x8] += A[16x16] * B[16x8]
__device__ __forceinline__ void mma_f16(float c[4], const unsigned a[4], const unsigned b[2]) {
    asm volatile(
        "mma.sync.aligned.m16n8k16.row.col.f32.f16.f16.f32 "
        "{%0,%1,%2,%3}, {%4,%5,%6,%7}, {%8,%9}, {%0,%1,%2,%3};\n"
        : "+f"(c[0]), "+f"(c[1]), "+f"(c[2]), "+f"(c[3])
        : "r"(a[0]), "r"(a[1]), "r"(a[2]), "r"(a[3]),
          "r"(b[0]), "r"(b[1]));
}

// ============================================================================
// fp32 -> fp16 conversion (vectorized), n4 = n/4
// ============================================================================
__global__ void __launch_bounds__(256)
f2h_kernel(const float* __restrict__ src, __half* __restrict__ dst, int n4)
{
    int i = blockIdx.x * blockDim.x + threadIdx.x;
    if (i < n4) {
        float4 v = ((const float4*)src)[i];
        __half2 a = __floats2half2_rn(v.x, v.y);
        __half2 b = __floats2half2_rn(v.z, v.w);
        ((__half2*)dst)[2 * i]     = a;
        ((__half2*)dst)[2 * i + 1] = b;
    }
}

// ============================================================================
// FP16-in GEMM (fp32 accum), CTA 128x128, warp 64x32, BK=16, double-buffered,
// dual-A concat. A/B sources are fp16 (halved gmem traffic, no in-loop CVT).
// Output: fp16 (C16) or fp32 (C32), epilogue relu(x+bias[col])*mask[row].
// SMEM layout identical to proven R8 kernel (conflict-free).
// ============================================================================
#define BM 128
#define BN 128
#define BK 16
#define ASTRIDE 12
#define BSTRIDE 136

__global__ void __launch_bounds__(256, 2)
hgemm16_kernel(const __half* __restrict__ A1, int K1,
               const __half* __restrict__ A2, int K2,
               const __half* __restrict__ Bm,
               float* __restrict__ C32, __half* __restrict__ C16,
               const float* __restrict__ bias, const float* __restrict__ mask,
               int N)
{
    __shared__ unsigned As[2][BM][ASTRIDE];
    __shared__ unsigned Bs[2][8][BSTRIDE];

    const int tid  = threadIdx.x;
    const int lane = tid & 31;
    const int warp = tid >> 5;
    const int gid  = lane >> 2;
    const int tig  = lane & 3;
    const int wm = (warp >> 2) * 64;
    const int wn = (warp & 3) * 32;

    const int rowBase = blockIdx.y * BM;
    const int colBase = blockIdx.x * BN;

    const int aR0 = tid >> 2;              // 0..63
    const int aH0 = (tid & 3) << 2;        // half offset in row chunk: 0/4/8/12
    const int aR1 = aR0 + 64;
    const int pr  = tid >> 5;              // 0..7 pair-row
    const int c0  = (tid & 31) << 2;       // 0..124

    const int K = K1 + K2;
    const int kChunks = K / BK;

    const __half* P1r0 = (K1 > 0) ? A1 + (size_t)(rowBase + aR0) * K1 : nullptr;
    const __half* P1r1 = (K1 > 0) ? A1 + (size_t)(rowBase + aR1) * K1 : nullptr;
    const __half* P2r0 = (K2 > 0) ? A2 + (size_t)(rowBase + aR0) * K2 - K1 : nullptr;
    const __half* P2r1 = (K2 > 0) ? A2 + (size_t)(rowBase + aR1) * K2 - K1 : nullptr;

    const __half* Blo = Bm + (size_t)(2 * pr)     * N + colBase + c0;
    const __half* Bhi = Bm + (size_t)(2 * pr + 1) * N + colBase + c0;

    float acc[4][4][4];
#pragma unroll
    for (int i = 0; i < 4; i++)
#pragma unroll
        for (int j = 0; j < 4; j++)
#pragma unroll
            for (int r = 0; r < 4; r++) acc[i][j][r] = 0.0f;

    // ---- prologue: prefetch chunk 0 (raw fp16 bits) ----
    uint2 ra0, ra1, rbl, rbh;
    {
        const __half* s0 = (0 < K1) ? P1r0 : P2r0;
        const __half* s1 = (0 < K1) ? P1r1 : P2r1;
        ra0 = *(const uint2*)(s0 + aH0);
        ra1 = *(const uint2*)(s1 + aH0);
        rbl = *(const uint2*)Blo;
        rbh = *(const uint2*)Bhi;
    }

    for (int ck = 0; ck < kChunks; ck++) {
        const int cur = ck & 1;

        // A: fp16 pairs already contiguous along k -> straight copy
        *(uint2*)&As[cur][aR0][aH0 >> 1] = ra0;
        *(uint2*)&As[cur][aR1][aH0 >> 1] = ra1;
        // B: interleave rows k,k+1 per column via PRMT
        {
            uint4 u;
            u.x = __byte_perm(rbl.x, rbh.x, 0x5410);
            u.y = __byte_perm(rbl.x, rbh.x, 0x7632);
            u.z = __byte_perm(rbl.y, rbh.y, 0x5410);
            u.w = __byte_perm(rbl.y, rbh.y, 0x7632);
            *(uint4*)&Bs[cur][pr][c0] = u;
        }
        __syncthreads();

        if (ck + 1 < kChunks) {
            const int k0n = (ck + 1) * BK;
            const __half* s0 = (k0n < K1) ? P1r0 : P2r0;
            const __half* s1 = (k0n < K1) ? P1r1 : P2r1;
            ra0 = *(const uint2*)(s0 + k0n + aH0);
            ra1 = *(const uint2*)(s1 + k0n + aH0);
            rbl = *(const uint2*)(Blo + (size_t)k0n * N);
            rbh = *(const uint2*)(Bhi + (size_t)k0n * N);
        }

        // fragments: scalar LDS (R8-proven conflict-free pattern)
        unsigned afr[4][4];
#pragma unroll
        for (int mt = 0; mt < 4; mt++) {
            const int r = wm + mt * 16 + gid;
            afr[mt][0] = As[cur][r][tig];
            afr[mt][1] = As[cur][r + 8][tig];
            afr[mt][2] = As[cur][r][tig + 4];
            afr[mt][3] = As[cur][r + 8][tig + 4];
        }
        unsigned bfr[4][2];
#pragma unroll
        for (int nt = 0; nt < 4; nt++) {
            const int c = wn + nt * 8 + gid;
            bfr[nt][0] = Bs[cur][tig][c];
            bfr[nt][1] = Bs[cur][tig + 4][c];
        }
#pragma unroll
        for (int mt = 0; mt < 4; mt++)
#pragma unroll
            for (int nt = 0; nt < 4; nt++)
                mma_f16(acc[mt][nt], afr[mt], bfr[nt]);
    }

    // ---- epilogue: relu(x + bias[col]) * mask[row]; fp16 or fp32 out ----
#pragma unroll
    for (int mt = 0; mt < 4; mt++) {
        const int r0 = rowBase + wm + mt * 16 + gid;
        const int r1 = r0 + 8;
        const float m0 = mask ? mask[r0] : 1.0f;
        const float m1 = mask ? mask[r1] : 1.0f;
#pragma unroll
        for (int nt = 0; nt < 4; nt++) {
            const int c = colBase + wn + nt * 8 + (tig << 1);
            const float b0 = bias[c], b1 = bias[c + 1];
            float v00 = fmaxf(acc[mt][nt][0] + b0, 0.0f) * m0;
            float v01 = fmaxf(acc[mt][nt][1] + b1, 0.0f) * m0;
            float v10 = fmaxf(acc[mt][nt][2] + b0, 0.0f) * m1;
            float v11 = fmaxf(acc[mt][nt][3] + b1, 0.0f) * m1;
            if (C16) {
                *(__half2*)(C16 + (size_t)r0 * N + c) = __floats2half2_rn(v00, v01);
                *(__half2*)(C16 + (size_t)r1 * N + c) = __floats2half2_rn(v10, v11);
            } else {
                float2 a = { v00, v01 }, b = { v10, v11 };
                *(float2*)(C32 + (size_t)r0 * N + c) = a;
                *(float2*)(C32 + (size_t)r1 * N + c) = b;
            }
        }
    }
}

// ============================================================================
// FP16 tensor-core flash attention, fp16 inputs + fp16 update output.
// Staging is raw copies (Q/K) and PRMT interleave (V) — no CVTs in loop.
// Compute core identical to proven R8 kernel.
// ============================================================================
struct AttnSmem3 {
    unsigned Qh[128][68];
    unsigned Kh[64][68];
    unsigned Vh[32][136];
    unsigned Ps[128][36];
    float    Mk[64];
};

__global__ void __launch_bounds__(256)
attn_mma_kernel(const __half* __restrict__ Tq, const __half* __restrict__ Tk,
                const float* __restrict__ maskK, __half* __restrict__ out)
{
    extern __shared__ char smem_raw[];
    AttnSmem3& sm = *reinterpret_cast<AttnSmem3*>(smem_raw);

    const int b  = blockIdx.z;
    const int h  = blockIdx.y;
    const int qt = blockIdx.x;
    const int tid  = threadIdx.x;
    const int lane = tid & 31;
    const int warp = tid >> 5;
    const int r0   = warp * 16;
    const int gid  = lane >> 2;
    const int tig  = lane & 3;
    const float SCALE = 0.08838834764831845f;

    // ---- load Q tile [128 x 128 halves] -> raw uint4 copies ----
    const __half* qbase = Tq + (size_t)(b * 512 + qt * 128) * 6144 + 2048 + h * 128;
#pragma unroll
    for (int it = 0; it < 8; it++) {
        int lin = it * 256 + tid;
        int r = lin >> 4, cu = (lin & 15) << 2;       // uint-pair offset
        uint4 u = *(const uint4*)(qbase + (size_t)r * 6144 + cu * 2);
        *(uint4*)&sm.Qh[r][cu] = u;
    }

    float m_i[2] = { -INFINITY, -INFINITY };
    float l_i[2] = { 0.0f, 0.0f };
    float oacc[16][4];
#pragma unroll
    for (int nt = 0; nt < 16; nt++)
#pragma unroll
        for (int j = 0; j < 4; j++) oacc[nt][j] = 0.0f;

    const __half* kbase = Tk + (size_t)b * 512 * 6144 + h * 128;
    const __half* vbase = kbase + 4096;

    const int vpr = tid >> 5;
    const int vc0 = (tid & 31) << 2;

    for (int kt = 0; kt < 8; kt++) {
        __syncthreads();

        // K: raw copies
#pragma unroll
        for (int it = 0; it < 4; it++) {
            int lin = it * 256 + tid;
            int r = lin >> 4, cu = (lin & 15) << 2;
            uint4 u = *(const uint4*)(kbase + (size_t)(kt * 64 + r) * 6144 + cu * 2);
            *(uint4*)&sm.Kh[r][cu] = u;
        }
        // V: interleave key rows 2p,2p+1 per d via PRMT
#pragma unroll
        for (int it = 0; it < 4; it++) {
            int p = it * 8 + vpr;
            uint2 lo = *(const uint2*)(vbase + (size_t)(kt * 64 + 2 * p)     * 6144 + vc0);
            uint2 hi = *(const uint2*)(vbase + (size_t)(kt * 64 + 2 * p + 1) * 6144 + vc0);
            uint4 u;
            u.x = __byte_perm(lo.x, hi.x, 0x5410);
            u.y = __byte_perm(lo.x, hi.x, 0x7632);
            u.z = __byte_perm(lo.y, hi.y, 0x5410);
            u.w = __byte_perm(lo.y, hi.y, 0x7632);
            *(uint4*)&sm.Vh[p][vc0] = u;
        }
        if (tid < 64) sm.Mk[tid] = maskK[b * 512 + kt * 64 + tid];
        __syncthreads();

        float c[8][4];
#pragma unroll
        for (int nt = 0; nt < 8; nt++)
#pragma unroll
            for (int j = 0; j < 4; j++) c[nt][j] = 0.0f;

#pragma unroll
        for (int ks = 0; ks < 8; ks++) {
            const int pd = ks * 8 + tig;
            unsigned a[4];
            a[0] = sm.Qh[r0 + gid][pd];
            a[1] = sm.Qh[r0 + gid + 8][pd];
            a[2] = sm.Qh[r0 + gid][pd + 4];
            a[3] = sm.Qh[r0 + gid + 8][pd + 4];
#pragma unroll
            for (int nt = 0; nt < 8; nt++) {
                unsigned bf[2];
                bf[0] = sm.Kh[nt * 8 + gid][pd];
                bf[1] = sm.Kh[nt * 8 + gid][pd + 4];
                mma_f16(c[nt], a, bf);
            }
        }

#pragma unroll
        for (int nt = 0; nt < 8; nt++) {
            const int col = nt * 8 + tig * 2;
            const float k0m = sm.Mk[col];
            const float k1m = sm.Mk[col + 1];
            c[nt][0] = (k0m != 0.0f) ? c[nt][0] * SCALE : -INFINITY;
            c[nt][1] = (k1m != 0.0f) ? c[nt][1] * SCALE : -INFINITY;
            c[nt][2] = (k0m != 0.0f) ? c[nt][2] * SCALE : -INFINITY;
            c[nt][3] = (k1m != 0.0f) ? c[nt][3] * SCALE : -INFINITY;
        }

#pragma unroll
        for (int j = 0; j < 2; j++) {
            float tmax = -INFINITY;
#pragma unroll
            for (int nt = 0; nt < 8; nt++)
                tmax = fmaxf(tmax, fmaxf(c[nt][j * 2], c[nt][j * 2 + 1]));
            tmax = fmaxf(tmax, __shfl_xor_sync(0xffffffffu, tmax, 1));
            tmax = fmaxf(tmax, __shfl_xor_sync(0xffffffffu, tmax, 2));
            float mnew  = fmaxf(m_i[j], tmax);
            float msafe = (mnew == -INFINITY) ? 0.0f : mnew;
            float corr  = __expf(m_i[j] - msafe);
            float lsum = 0.0f;
            const int row = r0 + gid + j * 8;
#pragma unroll
            for (int nt = 0; nt < 8; nt++) {
                float p0 = __expf(c[nt][j * 2]     - msafe);
                float p1 = __expf(c[nt][j * 2 + 1] - msafe);
                lsum += p0 + p1;
                __half2 ph = __floats2half2_rn(p0, p1);
                sm.Ps[row][nt * 4 + tig] = *(unsigned*)&ph;
            }
            lsum += __shfl_xor_sync(0xffffffffu, lsum, 1);
            lsum += __shfl_xor_sync(0xffffffffu, lsum, 2);
            l_i[j] = l_i[j] * corr + lsum;
            m_i[j] = mnew;
#pragma unroll
            for (int nt = 0; nt < 16; nt++) {
                oacc[nt][j * 2]     *= corr;
                oacc[nt][j * 2 + 1] *= corr;
            }
        }
        __syncwarp();

#pragma unroll
        for (int ks = 0; ks < 4; ks++) {
            const int pk = ks * 8 + tig;
            unsigned a[4];
            a[0] = sm.Ps[r0 + gid][pk];
            a[1] = sm.Ps[r0 + gid + 8][pk];
            a[2] = sm.Ps[r0 + gid][pk + 4];
            a[3] = sm.Ps[r0 + gid + 8][pk + 4];
#pragma unroll
            for (int nt = 0; nt < 16; nt++) {
                unsigned bf[2];
                bf[0] = sm.Vh[ks * 8 + tig][nt * 8 + gid];
                bf[1] = sm.Vh[ks * 8 + tig + 4][nt * 8 + gid];
                mma_f16(oacc[nt], a, bf);
            }
        }
    }

    // ---- write fp16 update ----
#pragma unroll
    for (int j = 0; j < 2; j++) {
        const float inv = (l_i[j] > 0.0f) ? (1.0f / l_i[j]) : 0.0f;
        const size_t orow = (size_t)(b * 512 + qt * 128 + r0 + gid + j * 8);
        __half* op = out + orow * 2048 + h * 128 + tig * 2;
#pragma unroll
        for (int nt = 0; nt < 16; nt++) {
            *(__half2*)(op + nt * 8) =
                __floats2half2_rn(oacc[nt][j * 2] * inv, oacc[nt][j * 2 + 1] * inv);
        }
    }
}

// ============================================================================
extern "C" void kernel_launch(void* const* d_in, const int* in_sizes, int n_in,
                              void* d_out, int out_size)
{
    (void)in_sizes; (void)n_in; (void)out_size;
    const float* v     = (const float*)d_in[0];
    const float* q     = (const float*)d_in[1];
    const float* vmask = (const float*)d_in[2];
    const float* qmask = (const float*)d_in[3];
    const float* Wv    = (const float*)d_in[4];
    const float* bv    = (const float*)d_in[5];
    const float* Wq    = (const float*)d_in[6];
    const float* bq    = (const float*)d_in[7];
    const float* Wvo   = (const float*)d_in[8];
    const float* bvo   = (const float*)d_in[9];
    const float* Wqo   = (const float*)d_in[10];
    const float* bqo   = (const float*)d_in[11];

    float* out_v = (float*)d_out;
    float* out_q = out_v + (size_t)ROWS * OS_W;

    __half *vh, *qh, *Wvh, *Wqh, *Wvoh, *Wqoh, *vtrans, *qtrans, *vupd, *qupd;
    cudaGetSymbolAddress((void**)&vh,     gh_v);
    cudaGetSymbolAddress((void**)&qh,     gh_q);
    cudaGetSymbolAddress((void**)&Wvh,    gh_Wv);
    cudaGetSymbolAddress((void**)&Wqh,    gh_Wq);
    cudaGetSymbolAddress((void**)&Wvoh,   gh_Wvo);
    cudaGetSymbolAddress((void**)&Wqoh,   gh_Wqo);
    cudaGetSymbolAddress((void**)&vtrans, gh_vtrans);
    cudaGetSymbolAddress((void**)&qtrans, gh_qtrans);
    cudaGetSymbolAddress((void**)&vupd,   gh_vupd);
    cudaGetSymbolAddress((void**)&qupd,   gh_qupd);

    cudaFuncSetAttribute(attn_mma_kernel, cudaFuncAttributeMaxDynamicSharedMemorySize,
                         (int)sizeof(AttnSmem3));

    dim3 blk(256);

    // 0) fp32 -> fp16 conversions (one-time per run)
    auto conv = [&](const float* s, __half* d, size_t n) {
        int n4 = (int)(n / 4);
        f2h_kernel<<<(n4 + 255) / 256, blk>>>(s, d, n4);
    };
    conv(v,   vh,   (size_t)ROWS * 2048);
    conv(q,   qh,   (size_t)ROWS * 1024);
    conv(Wv,  Wvh,  (size_t)2048 * TRANS_W);
    conv(Wq,  Wqh,  (size_t)1024 * TRANS_W);
    conv(Wvo, Wvoh, (size_t)4096 * OS_W);
    conv(Wqo, Wqoh, (size_t)3072 * OS_W);

    // 1) v_trans (fp16) = relu(v @ Wv + bv) * v_mask
    hgemm16_kernel<<<dim3(TRANS_W / BN, ROWS / BM), blk>>>(
        vh, 2048, nullptr, 0, Wvh, nullptr, vtrans, bv, vmask, TRANS_W);
    // 2) q_trans (fp16) = relu(q @ Wq + bq) * q_mask
    hgemm16_kernel<<<dim3(TRANS_W / BN, ROWS / BM), blk>>>(
        qh, 1024, nullptr, 0, Wqh, nullptr, qtrans, bq, qmask, TRANS_W);

    // 3) q2v attention -> v_update (fp16)
    attn_mma_kernel<<<dim3(4, 16, 16), blk, sizeof(AttnSmem3)>>>(vtrans, qtrans, qmask, vupd);
    // 4) v2q attention -> q_update (fp16)
    attn_mma_kernel<<<dim3(4, 16, 16), blk, sizeof(AttnSmem3)>>>(qtrans, vtrans, vmask, qupd);

    // 5) updated_v (fp32) = relu([v | v_update] @ Wvo + bvo)
    hgemm16_kernel<<<dim3(OS_W / BN, ROWS / BM), blk>>>(
        vh, 2048, vupd, 2048, Wvoh, out_v, nullptr, bvo, nullptr, OS_W);
    // 6) updated_q (fp32) = relu([q | q_update] @ Wqo + bqo)
    hgemm16_kernel<<<dim3(OS_W / BN, ROWS / BM), blk>>>(
        qh, 1024, qupd, 2048, Wqoh, out_q, nullptr, bqo, nullptr, OS_W);
}

// round 13
// speedup vs baseline: 1.1512x; 1.0202x over previous
#include <cuda_runtime.h>
#include <cuda_fp16.h>
#include <math.h>

// Problem constants: B=16, N=M=512, VS=2048, QS=1024, OS=2048, H=16, DH=128
#define ROWS      8192
#define TRANS_W   6144
#define OS_W      2048

// -------------------- fp16 scratch (device globals; no allocations) --------
__device__ __half gh_v     [(size_t)ROWS * 2048];
__device__ __half gh_q     [(size_t)ROWS * 1024];
__device__ __half gh_Wv    [(size_t)2048 * TRANS_W];
__device__ __half gh_Wq    [(size_t)1024 * TRANS_W];
__device__ __half gh_Wvo   [(size_t)4096 * OS_W];
__device__ __half gh_Wqo   [(size_t)3072 * OS_W];
__device__ __half gh_vtrans[(size_t)ROWS * TRANS_W];
__device__ __half gh_qtrans[(size_t)ROWS * TRANS_W];
__device__ __half gh_vupd  [(size_t)ROWS * OS_W];
__device__ __half gh_qupd  [(size_t)ROWS * OS_W];

__device__ __forceinline__ unsigned pack_h2(float lo, float hi) {
    __half2 h = __floats2half2_rn(lo, hi);
    return *(unsigned*)&h;
}

// fp16 MMA, fp32 accumulate: D[16x8] += A[16x16] * B[16x8]
__device__ __forceinline__ void mma_f16(float c[4], const unsigned a[4], const unsigned b[2]) {
    asm volatile(
        "mma.sync.aligned.m16n8k16.row.col.f32.f16.f16.f32 "
        "{%0,%1,%2,%3}, {%4,%5,%6,%7}, {%8,%9}, {%0,%1,%2,%3};\n"
        : "+f"(c[0]), "+f"(c[1]), "+f"(c[2]), "+f"(c[3])
        : "r"(a[0]), "r"(a[1]), "r"(a[2]), "r"(a[3]),
          "r"(b[0]), "r"(b[1]));
}

// ============================================================================
// fused fp32 -> fp16 conversion over all 6 tensors (one launch)
// segment sizes in float4 units (compile-time):
//   v 4194304 | q 2097152 | Wv 3145728 | Wq 1572864 | Wvo 2097152 | Wqo 1572864
//   total 14680064 = 57344 blocks x 256 threads exactly
// ============================================================================
#define C0 4194304
#define C1 6291456
#define C2 9437184
#define C3 11010048
#define C4 13107200
#define CONV_BLOCKS 57344

__global__ void __launch_bounds__(256)
f2h6_kernel(const float* __restrict__ s0, const float* __restrict__ s1,
            const float* __restrict__ s2, const float* __restrict__ s3,
            const float* __restrict__ s4, const float* __restrict__ s5,
            __half* __restrict__ d0, __half* __restrict__ d1,
            __half* __restrict__ d2, __half* __restrict__ d3,
            __half* __restrict__ d4, __half* __restrict__ d5)
{
    int i = blockIdx.x * blockDim.x + threadIdx.x;
    const float* s; __half* d; int off;
    if (i < C0)      { s = s0; d = d0; off = 0;  }
    else if (i < C1) { s = s1; d = d1; off = C0; }
    else if (i < C2) { s = s2; d = d2; off = C1; }
    else if (i < C3) { s = s3; d = d3; off = C2; }
    else if (i < C4) { s = s4; d = d4; off = C3; }
    else             { s = s5; d = d5; off = C4; }
    int j = i - off;
    float4 v = ((const float4*)s)[j];
    ((__half2*)d)[2 * j]     = __floats2half2_rn(v.x, v.y);
    ((__half2*)d)[2 * j + 1] = __floats2half2_rn(v.z, v.w);
}

// ============================================================================
// FP16-in GEMM (fp32 accum) — R11-proven core, with blockIdx.z selecting one
// of two fused problems (identical N). Dual-A concat per problem.
// ============================================================================
#define BM 128
#define BN 128
#define BK 16
#define ASTRIDE 12
#define BSTRIDE 136

struct GemmArgs {
    const __half* A1; const __half* A2; const __half* B;
    float* C32; __half* C16;
    const float* bias; const float* mask;
    int K1; int K2;
};

__global__ void __launch_bounds__(256, 2)
hgemm16_kernel(GemmArgs ga, GemmArgs gb, int N)
{
    const GemmArgs g = blockIdx.z ? gb : ga;
    const __half* __restrict__ A1 = g.A1;
    const __half* __restrict__ A2 = g.A2;
    const __half* __restrict__ Bm = g.B;
    float*  __restrict__ C32 = g.C32;
    __half* __restrict__ C16 = g.C16;
    const float* __restrict__ bias = g.bias;
    const float* __restrict__ mask = g.mask;
    const int K1 = g.K1, K2 = g.K2;

    __shared__ unsigned As[2][BM][ASTRIDE];
    __shared__ unsigned Bs[2][8][BSTRIDE];

    const int tid  = threadIdx.x;
    const int lane = tid & 31;
    const int warp = tid >> 5;
    const int gid  = lane >> 2;
    const int tig  = lane & 3;
    const int wm = (warp >> 2) * 64;
    const int wn = (warp & 3) * 32;

    const int rowBase = blockIdx.y * BM;
    const int colBase = blockIdx.x * BN;

    const int aR0 = tid >> 2;
    const int aH0 = (tid & 3) << 2;
    const int aR1 = aR0 + 64;
    const int pr  = tid >> 5;
    const int c0  = (tid & 31) << 2;

    const int K = K1 + K2;
    const int kChunks = K / BK;

    const __half* P1r0 = (K1 > 0) ? A1 + (size_t)(rowBase + aR0) * K1 : nullptr;
    const __half* P1r1 = (K1 > 0) ? A1 + (size_t)(rowBase + aR1) * K1 : nullptr;
    const __half* P2r0 = (K2 > 0) ? A2 + (size_t)(rowBase + aR0) * K2 - K1 : nullptr;
    const __half* P2r1 = (K2 > 0) ? A2 + (size_t)(rowBase + aR1) * K2 - K1 : nullptr;

    const __half* Blo = Bm + (size_t)(2 * pr)     * N + colBase + c0;
    const __half* Bhi = Bm + (size_t)(2 * pr + 1) * N + colBase + c0;

    float acc[4][4][4];
#pragma unroll
    for (int i = 0; i < 4; i++)
#pragma unroll
        for (int j = 0; j < 4; j++)
#pragma unroll
            for (int r = 0; r < 4; r++) acc[i][j][r] = 0.0f;

    uint2 ra0, ra1, rbl, rbh;
    {
        const __half* s0 = (0 < K1) ? P1r0 : P2r0;
        const __half* s1 = (0 < K1) ? P1r1 : P2r1;
        ra0 = *(const uint2*)(s0 + aH0);
        ra1 = *(const uint2*)(s1 + aH0);
        rbl = *(const uint2*)Blo;
        rbh = *(const uint2*)Bhi;
    }

    for (int ck = 0; ck < kChunks; ck++) {
        const int cur = ck & 1;

        *(uint2*)&As[cur][aR0][aH0 >> 1] = ra0;
        *(uint2*)&As[cur][aR1][aH0 >> 1] = ra1;
        {
            uint4 u;
            u.x = __byte_perm(rbl.x, rbh.x, 0x5410);
            u.y = __byte_perm(rbl.x, rbh.x, 0x7632);
            u.z = __byte_perm(rbl.y, rbh.y, 0x5410);
            u.w = __byte_perm(rbl.y, rbh.y, 0x7632);
            *(uint4*)&Bs[cur][pr][c0] = u;
        }
        __syncthreads();

        if (ck + 1 < kChunks) {
            const int k0n = (ck + 1) * BK;
            const __half* s0 = (k0n < K1) ? P1r0 : P2r0;
            const __half* s1 = (k0n < K1) ? P1r1 : P2r1;
            ra0 = *(const uint2*)(s0 + k0n + aH0);
            ra1 = *(const uint2*)(s1 + k0n + aH0);
            rbl = *(const uint2*)(Blo + (size_t)k0n * N);
            rbh = *(const uint2*)(Bhi + (size_t)k0n * N);
        }

        unsigned afr[4][4];
#pragma unroll
        for (int mt = 0; mt < 4; mt++) {
            const int r = wm + mt * 16 + gid;
            afr[mt][0] = As[cur][r][tig];
            afr[mt][1] = As[cur][r + 8][tig];
            afr[mt][2] = As[cur][r][tig + 4];
            afr[mt][3] = As[cur][r + 8][tig + 4];
        }
        unsigned bfr[4][2];
#pragma unroll
        for (int nt = 0; nt < 4; nt++) {
            const int c = wn + nt * 8 + gid;
            bfr[nt][0] = Bs[cur][tig][c];
            bfr[nt][1] = Bs[cur][tig + 4][c];
        }
#pragma unroll
        for (int mt = 0; mt < 4; mt++)
#pragma unroll
            for (int nt = 0; nt < 4; nt++)
                mma_f16(acc[mt][nt], afr[mt], bfr[nt]);
    }

#pragma unroll
    for (int mt = 0; mt < 4; mt++) {
        const int r0 = rowBase + wm + mt * 16 + gid;
        const int r1 = r0 + 8;
        const float m0 = mask ? mask[r0] : 1.0f;
        const float m1 = mask ? mask[r1] : 1.0f;
#pragma unroll
        for (int nt = 0; nt < 4; nt++) {
            const int c = colBase + wn + nt * 8 + (tig << 1);
            const float b0 = bias[c], b1 = bias[c + 1];
            float v00 = fmaxf(acc[mt][nt][0] + b0, 0.0f) * m0;
            float v01 = fmaxf(acc[mt][nt][1] + b1, 0.0f) * m0;
            float v10 = fmaxf(acc[mt][nt][2] + b0, 0.0f) * m1;
            float v11 = fmaxf(acc[mt][nt][3] + b1, 0.0f) * m1;
            if (C16) {
                *(__half2*)(C16 + (size_t)r0 * N + c) = __floats2half2_rn(v00, v01);
                *(__half2*)(C16 + (size_t)r1 * N + c) = __floats2half2_rn(v10, v11);
            } else {
                float2 a = { v00, v01 }, b = { v10, v11 };
                *(float2*)(C32 + (size_t)r0 * N + c) = a;
                *(float2*)(C32 + (size_t)r1 * N + c) = b;
            }
        }
    }
}

// ============================================================================
// FP16 tensor-core flash attention — R11-proven core; both directions fused
// via blockIdx.y in [0,32): dir = y>>4, h = y&15.
// ============================================================================
struct AttnSmem3 {
    unsigned Qh[128][68];
    unsigned Kh[64][68];
    unsigned Vh[32][136];
    unsigned Ps[128][36];
    float    Mk[64];
};

__global__ void __launch_bounds__(256)
attn_mma_kernel(const __half* __restrict__ vtrans, const __half* __restrict__ qtrans,
                const float* __restrict__ vmask, const float* __restrict__ qmask,
                __half* __restrict__ vupd, __half* __restrict__ qupd)
{
    extern __shared__ char smem_raw[];
    AttnSmem3& sm = *reinterpret_cast<AttnSmem3*>(smem_raw);

    const int b   = blockIdx.z;
    const int hd  = blockIdx.y;
    const int dir = hd >> 4;
    const int h   = hd & 15;
    const int qt  = blockIdx.x;

    const __half* Tq    = dir ? qtrans : vtrans;
    const __half* Tk    = dir ? vtrans : qtrans;
    const float*  maskK = dir ? vmask  : qmask;
    __half*       out   = dir ? qupd   : vupd;

    const int tid  = threadIdx.x;
    const int lane = tid & 31;
    const int warp = tid >> 5;
    const int r0   = warp * 16;
    const int gid  = lane >> 2;
    const int tig  = lane & 3;
    const float SCALE = 0.08838834764831845f;

    const __half* qbase = Tq + (size_t)(b * 512 + qt * 128) * 6144 + 2048 + h * 128;
#pragma unroll
    for (int it = 0; it < 8; it++) {
        int lin = it * 256 + tid;
        int r = lin >> 4, cu = (lin & 15) << 2;
        uint4 u = *(const uint4*)(qbase + (size_t)r * 6144 + cu * 2);
        *(uint4*)&sm.Qh[r][cu] = u;
    }

    float m_i[2] = { -INFINITY, -INFINITY };
    float l_i[2] = { 0.0f, 0.0f };
    float oacc[16][4];
#pragma unroll
    for (int nt = 0; nt < 16; nt++)
#pragma unroll
        for (int j = 0; j < 4; j++) oacc[nt][j] = 0.0f;

    const __half* kbase = Tk + (size_t)b * 512 * 6144 + h * 128;
    const __half* vbase = kbase + 4096;

    const int vpr = tid >> 5;
    const int vc0 = (tid & 31) << 2;

    for (int kt = 0; kt < 8; kt++) {
        __syncthreads();
#pragma unroll
        for (int it = 0; it < 4; it++) {
            int lin = it * 256 + tid;
            int r = lin >> 4, cu = (lin & 15) << 2;
            uint4 u = *(const uint4*)(kbase + (size_t)(kt * 64 + r) * 6144 + cu * 2);
            *(uint4*)&sm.Kh[r][cu] = u;
        }
#pragma unroll
        for (int it = 0; it < 4; it++) {
            int p = it * 8 + vpr;
            uint2 lo = *(const uint2*)(vbase + (size_t)(kt * 64 + 2 * p)     * 6144 + vc0);
            uint2 hi = *(const uint2*)(vbase + (size_t)(kt * 64 + 2 * p + 1) * 6144 + vc0);
            uint4 u;
            u.x = __byte_perm(lo.x, hi.x, 0x5410);
            u.y = __byte_perm(lo.x, hi.x, 0x7632);
            u.z = __byte_perm(lo.y, hi.y, 0x5410);
            u.w = __byte_perm(lo.y, hi.y, 0x7632);
            *(uint4*)&sm.Vh[p][vc0] = u;
        }
        if (tid < 64) sm.Mk[tid] = maskK[b * 512 + kt * 64 + tid];
        __syncthreads();

        float c[8][4];
#pragma unroll
        for (int nt = 0; nt < 8; nt++)
#pragma unroll
            for (int j = 0; j < 4; j++) c[nt][j] = 0.0f;

#pragma unroll
        for (int ks = 0; ks < 8; ks++) {
            const int pd = ks * 8 + tig;
            unsigned a[4];
            a[0] = sm.Qh[r0 + gid][pd];
            a[1] = sm.Qh[r0 + gid + 8][pd];
            a[2] = sm.Qh[r0 + gid][pd + 4];
            a[3] = sm.Qh[r0 + gid + 8][pd + 4];
#pragma unroll
            for (int nt = 0; nt < 8; nt++) {
                unsigned bf[2];
                bf[0] = sm.Kh[nt * 8 + gid][pd];
                bf[1] = sm.Kh[nt * 8 + gid][pd + 4];
                mma_f16(c[nt], a, bf);
            }
        }

#pragma unroll
        for (int nt = 0; nt < 8; nt++) {
            const int col = nt * 8 + tig * 2;
            const float k0m = sm.Mk[col];
            const float k1m = sm.Mk[col + 1];
            c[nt][0] = (k0m != 0.0f) ? c[nt][0] * SCALE : -INFINITY;
            c[nt][1] = (k1m != 0.0f) ? c[nt][1] * SCALE : -INFINITY;
            c[nt][2] = (k0m != 0.0f) ? c[nt][2] * SCALE : -INFINITY;
            c[nt][3] = (k1m != 0.0f) ? c[nt][3] * SCALE : -INFINITY;
        }

#pragma unroll
        for (int j = 0; j < 2; j++) {
            float tmax = -INFINITY;
#pragma unroll
            for (int nt = 0; nt < 8; nt++)
                tmax = fmaxf(tmax, fmaxf(c[nt][j * 2], c[nt][j * 2 + 1]));
            tmax = fmaxf(tmax, __shfl_xor_sync(0xffffffffu, tmax, 1));
            tmax = fmaxf(tmax, __shfl_xor_sync(0xffffffffu, tmax, 2));
            float mnew  = fmaxf(m_i[j], tmax);
            float msafe = (mnew == -INFINITY) ? 0.0f : mnew;
            float corr  = __expf(m_i[j] - msafe);
            float lsum = 0.0f;
            const int row = r0 + gid + j * 8;
#pragma unroll
            for (int nt = 0; nt < 8; nt++) {
                float p0 = __expf(c[nt][j * 2]     - msafe);
                float p1 = __expf(c[nt][j * 2 + 1] - msafe);
                lsum += p0 + p1;
                sm.Ps[row][nt * 4 + tig] = pack_h2(p0, p1);
            }
            lsum += __shfl_xor_sync(0xffffffffu, lsum, 1);
            lsum += __shfl_xor_sync(0xffffffffu, lsum, 2);
            l_i[j] = l_i[j] * corr + lsum;
            m_i[j] = mnew;
#pragma unroll
            for (int nt = 0; nt < 16; nt++) {
                oacc[nt][j * 2]     *= corr;
                oacc[nt][j * 2 + 1] *= corr;
            }
        }
        __syncwarp();

#pragma unroll
        for (int ks = 0; ks < 4; ks++) {
            const int pk = ks * 8 + tig;
            unsigned a[4];
            a[0] = sm.Ps[r0 + gid][pk];
            a[1] = sm.Ps[r0 + gid + 8][pk];
            a[2] = sm.Ps[r0 + gid][pk + 4];
            a[3] = sm.Ps[r0 + gid + 8][pk + 4];
#pragma unroll
            for (int nt = 0; nt < 16; nt++) {
                unsigned bf[2];
                bf[0] = sm.Vh[ks * 8 + tig][nt * 8 + gid];
                bf[1] = sm.Vh[ks * 8 + tig + 4][nt * 8 + gid];
                mma_f16(oacc[nt], a, bf);
            }
        }
    }

#pragma unroll
    for (int j = 0; j < 2; j++) {
        const float inv = (l_i[j] > 0.0f) ? (1.0f / l_i[j]) : 0.0f;
        const size_t orow = (size_t)(b * 512 + qt * 128 + r0 + gid + j * 8);
        __half* op = out + orow * 2048 + h * 128 + tig * 2;
#pragma unroll
        for (int nt = 0; nt < 16; nt++) {
            *(__half2*)(op + nt * 8) =
                __floats2half2_rn(oacc[nt][j * 2] * inv, oacc[nt][j * 2 + 1] * inv);
        }
    }
}

// ============================================================================
extern "C" void kernel_launch(void* const* d_in, const int* in_sizes, int n_in,
                              void* d_out, int out_size)
{
    (void)in_sizes; (void)n_in; (void)out_size;
    const float* v     = (const float*)d_in[0];
    const float* q     = (const float*)d_in[1];
    const float* vmask = (const float*)d_in[2];
    const float* qmask = (const float*)d_in[3];
    const float* Wv    = (const float*)d_in[4];
    const float* bv    = (const float*)d_in[5];
    const float* Wq    = (const float*)d_in[6];
    const float* bq    = (const float*)d_in[7];
    const float* Wvo   = (const float*)d_in[8];
    const float* bvo   = (const float*)d_in[9];
    const float* Wqo   = (const float*)d_in[10];
    const float* bqo   = (const float*)d_in[11];

    float* out_v = (float*)d_out;
    float* out_q = out_v + (size_t)ROWS * OS_W;

    __half *vh, *qh, *Wvh, *Wqh, *Wvoh, *Wqoh, *vtrans, *qtrans, *vupd, *qupd;
    cudaGetSymbolAddress((void**)&vh,     gh_v);
    cudaGetSymbolAddress((void**)&qh,     gh_q);
    cudaGetSymbolAddress((void**)&Wvh,    gh_Wv);
    cudaGetSymbolAddress((void**)&Wqh,    gh_Wq);
    cudaGetSymbolAddress((void**)&Wvoh,   gh_Wvo);
    cudaGetSymbolAddress((void**)&Wqoh,   gh_Wqo);
    cudaGetSymbolAddress((void**)&vtrans, gh_vtrans);
    cudaGetSymbolAddress((void**)&qtrans, gh_qtrans);
    cudaGetSymbolAddress((void**)&vupd,   gh_vupd);
    cudaGetSymbolAddress((void**)&qupd,   gh_qupd);

    cudaFuncSetAttribute(attn_mma_kernel, cudaFuncAttributeMaxDynamicSharedMemorySize,
                         (int)sizeof(AttnSmem3));

    dim3 blk(256);

    // 0) all fp32 -> fp16 conversions in ONE launch
    f2h6_kernel<<<CONV_BLOCKS, blk>>>(v, q, Wv, Wq, Wvo, Wqo,
                                      vh, qh, Wvh, Wqh, Wvoh, Wqoh);

    // 1+2) fused: v_trans / q_trans
    {
        GemmArgs ga = { vh, nullptr, Wvh, nullptr, vtrans, bv, vmask, 2048, 0 };
        GemmArgs gb = { qh, nullptr, Wqh, nullptr, qtrans, bq, qmask, 1024, 0 };
        hgemm16_kernel<<<dim3(TRANS_W / BN, ROWS / BM, 2), blk>>>(ga, gb, TRANS_W);
    }

    // 3+4) fused bidirectional attention
    attn_mma_kernel<<<dim3(4, 32, 16), blk, sizeof(AttnSmem3)>>>(
        vtrans, qtrans, vmask, qmask, vupd, qupd);

    // 5+6) fused: updated_v / updated_q (concat GEMMs, fp32 out)
    {
        GemmArgs ga = { vh, vupd, Wvoh, out_v, nullptr, bvo, nullptr, 2048, 2048 };
        GemmArgs gb = { qh, qupd, Wqoh, out_q, nullptr, bqo, nullptr, 1024, 2048 };
        hgemm16_kernel<<<dim3(OS_W / BN, ROWS / BM, 2), blk>>>(ga, gb, OS_W);
    }
}